// round 13
// baseline (speedup 1.0000x reference)
#include <cuda_runtime.h>
#include <cuda_fp16.h>
#include <cstdint>

// Problem shape (dataset-fixed): N=100000 voxels, C=128, K=27 offsets, M=50000 pairs.
#define CCH 128
#define MAXELEM (100000 * 128)

__device__ float    d_tmp[2 * MAXELEM];   // conv1 / conv2 raw fp32 outputs
__device__ uint32_t d_xh[MAXELEM / 2];    // fp16-packed x (conv1 input)
__device__ uint32_t d_t1h[MAXELEM / 2];   // fp16-packed relu(bn1(tmp1)) (conv2 input)
__device__ float    d_part1[148 * 256];
__device__ float    d_part2[148 * 256];

// ---------------- smem layout (bytes) ----------------
// A tiles: 8 buffers (4 per half) of 64 rows x 136 halves (272B/row).
// W tile: 128 couts x 136 halves. idx rings: 2 halves x 8 slots x 128 ints.
#define AROW_B    272
#define A_TILE_B  (64 * AROW_B)             // 17408
#define W_OFF_B   (8 * A_TILE_B)            // 139264
#define W_TILE_B  (128 * AROW_B)            // 34816
#define IDX_OFF_B (W_OFF_B + W_TILE_B)      // 174080
#define SMEM_BYTES (IDX_OFF_B + 2 * 8 * 128 * 4)   // 182272

// ---------------- helpers ----------------
__device__ __forceinline__ uint32_t s2u(const void* p) {
    uint32_t a;
    asm("{ .reg .u64 t; cvta.to.shared.u64 t, %1; cvt.u32.u64 %0, t; }" : "=r"(a) : "l"(p));
    return a;
}
__device__ __forceinline__ void barh(int id) {
    asm volatile("bar.sync %0, 256;" :: "r"(id) : "memory");
}
__device__ __forceinline__ void mma_f16(float* d, uint32_t a0, uint32_t a1, uint32_t a2,
                                        uint32_t a3, uint32_t b0, uint32_t b1) {
    asm volatile(
        "mma.sync.aligned.m16n8k16.row.col.f32.f16.f16.f32 "
        "{%0,%1,%2,%3}, {%4,%5,%6,%7}, {%8,%9}, {%0,%1,%2,%3};"
        : "+f"(d[0]), "+f"(d[1]), "+f"(d[2]), "+f"(d[3])
        : "r"(a0), "r"(a1), "r"(a2), "r"(a3), "r"(b0), "r"(b1));
}
__device__ __forceinline__ void red4(float* p, float a, float b, float c, float d) {
    asm volatile("red.global.add.v4.f32 [%0], {%1,%2,%3,%4};"
                 :: "l"(p), "f"(a), "f"(b), "f"(c), "f"(d) : "memory");
}
__device__ __forceinline__ void cpa16(uint32_t dst, const void* src, int sbytes) {
    asm volatile("cp.async.cg.shared.global [%0], [%1], 16, %2;"
                 :: "r"(dst), "l"(src), "r"(sbytes) : "memory");
}
__device__ __forceinline__ uint32_t pack2(float a, float b) {
    __half2 h = __floats2half2_rn(a, b);
    return *reinterpret_cast<uint32_t*>(&h);
}

// ---------------------------------------------------------------------------
// persistent fused conv, fp16 + quad-buffer edition:
// 512 threads = 2 independent 256-thread halves. Per half: FOUR 64-row fp16
// A buffers (cp.async, wait_group 1), 8-slot idx ring, ONE named barrier per
// tile (quad buffering makes the post-mma barrier provably unnecessary:
// buf (i+2)&3 was last read at iter i-2, and the iter-start barrier bounds
// warp skew to one iteration). mma.m16n8k16 f16->f32; register-direct
// red.global.add.v4 scatter issued right after each warp's mma.
// ---------------------------------------------------------------------------
__global__ __launch_bounds__(512, 1)
void conv_tc(const uint32_t* __restrict__ xh, const float* __restrict__ w,
             const int* __restrict__ idx_in, const int* __restrict__ idx_out,
             float* __restrict__ out, int M, int SMT, int TT, int PER)
{
    extern __shared__ __align__(16) char smc[];
    uint32_t* Ww  = (uint32_t*)(smc + W_OFF_B);
    __half*   Wh  = (__half*)(smc + W_OFF_B);
    int*      Ism = (int*)(smc + IDX_OFF_B);
    const int tid = threadIdx.x, lane = tid & 31, warp = tid >> 5;
    const int half = warp >> 3;
    const int hwarp = warp & 7;
    const int htid = tid & 255;
    const int barid = 1 + half;

    int t0 = blockIdx.x * PER;
    int t1 = t0 + PER; if (t1 > TT) t1 = TT;
    if (t0 >= t1) return;

    char* Ah = smc + half * (4 * A_TILE_B);
    int*  Ih = Ism + half * (8 * 128);
    const uint32_t ahu = s2u(Ah);
    const uint32_t ihu = s2u(Ih);

    // synchronous preload of idx for t0, t0+1 (this half's 64 rows)
    for (int t = t0; t < t0 + 2 && t < t1; t++) {
        int k = t / SMT, smt = t - k * SMT, m0 = smt * 128 + half * 64;
        int nr = M - m0; if (nr > 64) nr = 64; if (nr < 0) nr = 0;
        int* slot = Ih + (t & 7) * 128;
        if (htid < 64)       slot[htid] = (htid < nr) ? __ldg(idx_in + (size_t)k * M + m0 + htid) : 0;
        else if (htid < 128) slot[htid] = ((htid - 64) < nr) ? __ldg(idx_out + (size_t)k * M + m0 + (htid - 64)) : 0;
    }
    __syncthreads();

    // gather this half's 64 fp16 rows (256B = 16 chunks) + idx prefetch t+2
    auto issue_gather = [&](int t) {
        int k = t / SMT, smt = t - k * SMT, m0 = smt * 128 + half * 64;
        int nr = M - m0; if (nr > 64) nr = 64; if (nr < 0) nr = 0;
        const int* slot = Ih + (t & 7) * 128;
        uint32_t ab = ahu + (uint32_t)(t & 3) * A_TILE_B;
        #pragma unroll
        for (int j = 0; j < 4; j++) {
            int id = htid + j * 256;
            int row = id >> 4, s = id & 15;
            int ok = (row < nr);
            int src = ok ? slot[row] : 0;
            cpa16(ab + (uint32_t)(row * AROW_B + s * 16),
                  (const char*)xh + (size_t)src * 256 + s * 16, ok ? 16 : 0);
        }
        int tn = t + 2;
        if (tn < t1 && htid < 32) {
            int k2 = tn / SMT, smt2 = tn - k2 * SMT, m02 = smt2 * 128 + half * 64;
            int nr2 = M - m02; if (nr2 > 64) nr2 = 64; if (nr2 < 0) nr2 = 0;
            int r = (htid & 15) * 4;
            const int* g = (htid < 16) ? (idx_in  + (size_t)k2 * M + m02)
                                       : (idx_out + (size_t)k2 * M + m02);
            uint32_t sdst = ihu + (uint32_t)(((tn & 7) * 128) + ((htid < 16) ? 0 : 64) + r) * 4;
            int nb = (r + 4 <= nr2) ? 16 : ((r < nr2) ? (nr2 - r) * 4 : 0);
            cpa16(sdst, g + r, nb);
        }
        asm volatile("cp.async.commit_group;" ::: "memory");
    };

    issue_gather(t0);
    if (t0 + 1 < t1) issue_gather(t0 + 1);

    int kcur = -1;
    const int wm = hwarp & 1, wn = hwarp >> 1;   // 2x4 warp grid over 64x128
    const int gr = lane >> 2, tg = lane & 3;
    const bool oddlane = (lane & 1);

    for (int i = t0; i < t1; i++) {
        int k = i / SMT, smt = i - k * SMT, m0 = smt * 128 + half * 64;
        int nr = M - m0; if (nr > 64) nr = 64; if (nr < 0) nr = 0;
        const uint32_t* Aw = (const uint32_t*)(Ah + (i & 3) * A_TILE_B);
        const int* slot = Ih + (i & 7) * 128;

        if (i + 1 < t1) asm volatile("cp.async.wait_group 1;" ::: "memory");
        else            asm volatile("cp.async.wait_group 0;" ::: "memory");
        barh(barid);     // A tile i + idx slot i+2 visible to all half-threads

        if (k != kcur) {                       // rare: both halves at same i
            __syncthreads();
            const float* wk = w + (size_t)k * (CCH * CCH);
            #pragma unroll 4
            for (int j = 0; j < 32; j++) {
                int idx = tid + j * 512;
                int cin = idx >> 7, cout = idx & 127;
                Wh[cout * 136 + cin] = __float2half_rn(wk[idx]);
            }
            kcur = k;
            __syncthreads();
        }

        float acc[2][4][4];
        #pragma unroll
        for (int a = 0; a < 2; a++)
            #pragma unroll
            for (int b = 0; b < 4; b++)
                #pragma unroll
                for (int c = 0; c < 4; c++) acc[a][b][c] = 0.f;

        const int rbase = wm * 32 + gr;        // row word stride = 68

        #pragma unroll
        for (int ks = 0; ks < 8; ks++) {
            uint32_t b0[4], b1[4];
            #pragma unroll
            for (int nf = 0; nf < 4; nf++) {
                int col = wn * 32 + nf * 8 + gr;
                b0[nf] = Ww[col * 68 + ks * 8 + tg];
                b1[nf] = Ww[col * 68 + ks * 8 + tg + 4];
            }
            #pragma unroll
            for (int mf = 0; mf < 2; mf++) {
                int r = rbase + mf * 16;
                uint32_t a0 = Aw[r * 68 + ks * 8 + tg];
                uint32_t a1 = Aw[(r + 8) * 68 + ks * 8 + tg];
                uint32_t a2 = Aw[r * 68 + ks * 8 + tg + 4];
                uint32_t a3 = Aw[(r + 8) * 68 + ks * 8 + tg + 4];
                #pragma unroll
                for (int nf = 0; nf < 4; nf++)
                    mma_f16(acc[mf][nf], a0, a1, a2, a3, b0[nf], b1[nf]);
            }
        }

        // quad buffering: no barrier needed before refilling buf (i+2)&3
        if (i + 2 < t1) issue_gather(i + 2);

        // lane-balanced register-direct scatter
        const int* oslot = slot + 64;
        #pragma unroll
        for (int mf = 0; mf < 2; mf++) {
            #pragma unroll
            for (int rh = 0; rh < 2; rh++) {
                int r = wm * 32 + mf * 16 + rh * 8 + gr;
                int dst = (r < nr) ? oslot[r] : -1;
                #pragma unroll
                for (int nf = 0; nf < 4; nf++) {
                    float c0 = acc[mf][nf][rh * 2 + 0];
                    float c1 = acc[mf][nf][rh * 2 + 1];
                    float q0 = __shfl_xor_sync(0xFFFFFFFFu, c0, 1);
                    float q1 = __shfl_xor_sync(0xFFFFFFFFu, c1, 1);
                    bool mine = (((nf & 1) ^ (lane & 1)) == 0);
                    if (mine && dst >= 0) {
                        float a0 = oddlane ? q0 : c0, a1 = oddlane ? q1 : c1;
                        float a2 = oddlane ? c0 : q0, a3 = oddlane ? c1 : q1;
                        int col = wn * 32 + nf * 8 + (tg & 2) * 2;
                        red4(out + (size_t)dst * CCH + col, a0, a1, a2, a3);
                    }
                }
            }
        }
    }
}

// ---------------- tiny shim kernels (profiling alignment, ~1us each) -------
__global__ void shim_kernel(float* p) { if (threadIdx.x == 1023) p[0] = 0.f; }

// ---------------- pack x -> fp16 ----------------
__global__ __launch_bounds__(512)
void pack_x(const float* __restrict__ x, uint32_t* __restrict__ xh, int total32)
{
    const int stride = gridDim.x * blockDim.x;
    for (int i = blockIdx.x * blockDim.x + threadIdx.x; i < total32; i += 2 * stride) {
        int i2 = i + stride;
        float4 v = reinterpret_cast<const float4*>(x)[i];
        float4 u = (i2 < total32) ? reinterpret_cast<const float4*>(x)[i2]
                                  : make_float4(0.f, 0.f, 0.f, 0.f);
        reinterpret_cast<uint2*>(xh)[i] = make_uint2(pack2(v.x, v.y), pack2(v.z, v.w));
        if (i2 < total32)
            reinterpret_cast<uint2*>(xh)[i2] = make_uint2(pack2(u.x, u.y), pack2(u.z, u.w));
    }
}

// ---------------- BN stats: vectorized float4, per-block partials ----------
__global__ __launch_bounds__(512)
void bn_stats(const float* __restrict__ t, int N, float* __restrict__ part)
{
    __shared__ float sh[16 * 128], sh2[16 * 128];
    const int cg = threadIdx.x & 31;
    const int rs = threadIdx.x >> 5;
    float4 s  = make_float4(0.f, 0.f, 0.f, 0.f);
    float4 s2 = make_float4(0.f, 0.f, 0.f, 0.f);
    for (int r = blockIdx.x * 16 + rs; r < N; r += gridDim.x * 16) {
        float4 v = reinterpret_cast<const float4*>(t)[(size_t)r * 32 + cg];
        s.x += v.x; s.y += v.y; s.z += v.z; s.w += v.w;
        s2.x = fmaf(v.x, v.x, s2.x); s2.y = fmaf(v.y, v.y, s2.y);
        s2.z = fmaf(v.z, v.z, s2.z); s2.w = fmaf(v.w, v.w, s2.w);
    }
    reinterpret_cast<float4*>(sh)[rs * 32 + cg]  = s;
    reinterpret_cast<float4*>(sh2)[rs * 32 + cg] = s2;
    __syncthreads();
    if (threadIdx.x < 128) {
        int c = threadIdx.x;
        float ss = 0.f, ss2 = 0.f;
        #pragma unroll
        for (int j = 0; j < 16; j++) {
            ss  += sh[j * 128 + c];
            ss2 += sh2[j * 128 + c];
        }
        part[blockIdx.x * 256 + c]       = ss;
        part[blockIdx.x * 256 + 128 + c] = ss2;
    }
}

__device__ __forceinline__ void make_sb(const float* __restrict__ part,
                                        const float* __restrict__ gamma,
                                        const float* __restrict__ beta,
                                        float invN, float* sb)
{
    if (threadIdx.x < 128) {
        int c = threadIdx.x;
        float s = 0.f, s2 = 0.f;
        #pragma unroll 4
        for (int b = 0; b < 148; b++) {
            s  += part[b * 256 + c];
            s2 += part[b * 256 + 128 + c];
        }
        float mean = s * invN;
        float var  = s2 * invN - mean * mean;
        float sc   = gamma[c] * rsqrtf(var + 1e-5f);
        sb[c]       = sc;
        sb[128 + c] = beta[c] - mean * sc;
    }
    __syncthreads();
}

// bn1 + relu -> fp16 packed (conv2 input)
__global__ __launch_bounds__(512)
void bn_apply(const float* __restrict__ t, const float* __restrict__ part,
              const float* __restrict__ gamma, const float* __restrict__ beta,
              uint32_t* __restrict__ o, int total32, float invN)
{
    __shared__ float sb[256];
    make_sb(part, gamma, beta, invN, sb);
    const int stride = gridDim.x * blockDim.x;
    for (int i = blockIdx.x * blockDim.x + threadIdx.x; i < total32; i += 2 * stride) {
        int i2 = i + stride;
        float4 v = reinterpret_cast<const float4*>(t)[i];
        float4 u = (i2 < total32) ? reinterpret_cast<const float4*>(t)[i2]
                                  : make_float4(0.f, 0.f, 0.f, 0.f);
        int c = (i & 31) * 4;
        v.x = fmaxf(fmaf(v.x, sb[c + 0], sb[128 + c + 0]), 0.f);
        v.y = fmaxf(fmaf(v.y, sb[c + 1], sb[128 + c + 1]), 0.f);
        v.z = fmaxf(fmaf(v.z, sb[c + 2], sb[128 + c + 2]), 0.f);
        v.w = fmaxf(fmaf(v.w, sb[c + 3], sb[128 + c + 3]), 0.f);
        reinterpret_cast<uint2*>(o)[i] = make_uint2(pack2(v.x, v.y), pack2(v.z, v.w));
        if (i2 < total32) {
            int c2 = (i2 & 31) * 4;
            u.x = fmaxf(fmaf(u.x, sb[c2 + 0], sb[128 + c2 + 0]), 0.f);
            u.y = fmaxf(fmaf(u.y, sb[c2 + 1], sb[128 + c2 + 1]), 0.f);
            u.z = fmaxf(fmaf(u.z, sb[c2 + 2], sb[128 + c2 + 2]), 0.f);
            u.w = fmaxf(fmaf(u.w, sb[c2 + 3], sb[128 + c2 + 3]), 0.f);
            reinterpret_cast<uint2*>(o)[i2] = make_uint2(pack2(u.x, u.y), pack2(u.z, u.w));
        }
    }
}

// out = relu(bn2(conv2) + identity)
__global__ __launch_bounds__(512)
void final_kernel(const float* __restrict__ t2, const float* __restrict__ x,
                  const float* __restrict__ part,
                  const float* __restrict__ gamma, const float* __restrict__ beta,
                  float* __restrict__ out, int total4, float invN)
{
    __shared__ float sb[256];
    make_sb(part, gamma, beta, invN, sb);
    const int stride = gridDim.x * blockDim.x;
    for (int i = blockIdx.x * blockDim.x + threadIdx.x; i < total4; i += 2 * stride) {
        int i2 = i + stride;
        float4 v  = reinterpret_cast<const float4*>(t2)[i];
        float4 xi = reinterpret_cast<const float4*>(x)[i];
        int c = (i & 31) * 4;
        float4 o;
        o.x = fmaxf(fmaf(v.x, sb[c + 0], sb[128 + c + 0]) + xi.x, 0.f);
        o.y = fmaxf(fmaf(v.y, sb[c + 1], sb[128 + c + 1]) + xi.y, 0.f);
        o.z = fmaxf(fmaf(v.z, sb[c + 2], sb[128 + c + 2]) + xi.z, 0.f);
        o.w = fmaxf(fmaf(v.w, sb[c + 3], sb[128 + c + 3]) + xi.w, 0.f);
        reinterpret_cast<float4*>(out)[i] = o;
        if (i2 < total4) {
            float4 v2 = reinterpret_cast<const float4*>(t2)[i2];
            float4 x2 = reinterpret_cast<const float4*>(x)[i2];
            int c2 = (i2 & 31) * 4;
            float4 o2;
            o2.x = fmaxf(fmaf(v2.x, sb[c2 + 0], sb[128 + c2 + 0]) + x2.x, 0.f);
            o2.y = fmaxf(fmaf(v2.y, sb[c2 + 1], sb[128 + c2 + 1]) + x2.y, 0.f);
            o2.z = fmaxf(fmaf(v2.z, sb[c2 + 2], sb[128 + c2 + 2]) + x2.z, 0.f);
            o2.w = fmaxf(fmaf(v2.w, sb[c2 + 3], sb[128 + c2 + 3]) + x2.w, 0.f);
            reinterpret_cast<float4*>(out)[i2] = o2;
        }
    }
}

// ---------------- launch ----------------
extern "C" void kernel_launch(void* const* d_in, const int* in_sizes, int n_in,
                              void* d_out, int out_size)
{
    const float* x      = (const float*)d_in[0];
    const float* w1     = (const float*)d_in[1];
    const float* gamma1 = (const float*)d_in[2];
    const float* beta1  = (const float*)d_in[3];
    const float* w2     = (const float*)d_in[4];
    const float* gamma2 = (const float*)d_in[5];
    const float* beta2  = (const float*)d_in[6];
    const int*   idx_in  = (const int*)d_in[7];
    const int*   idx_out = (const int*)d_in[8];
    float* out = (float*)d_out;

    const int N = in_sizes[0] / CCH;           // 100000
    const int K = in_sizes[1] / (CCH * CCH);   // 27
    const int M = in_sizes[7] / K;             // 50000
    const int SMT = (M + 127) / 128;           // 128-row super-tiles per offset
    const int TT = K * SMT;                    // total super-tiles
    const int GRID = 148;
    const int PER = (TT + GRID - 1) / GRID;

    cudaStream_t s = 0;

    float *tmp, *part1, *part2;
    uint32_t *xh, *t1h;
    cudaGetSymbolAddress((void**)&tmp,   d_tmp);
    cudaGetSymbolAddress((void**)&xh,    d_xh);
    cudaGetSymbolAddress((void**)&t1h,   d_t1h);
    cudaGetSymbolAddress((void**)&part1, d_part1);
    cudaGetSymbolAddress((void**)&part2, d_part2);
    float* tmp1 = tmp;
    float* tmp2 = tmp + (size_t)MAXELEM;

    size_t nb = (size_t)N * CCH * sizeof(float);
    cudaMemsetAsync(tmp1, 0, 2 * nb, s);       // splits into 2 launches (>64MB)

    cudaFuncSetAttribute(conv_tc, cudaFuncAttributeMaxDynamicSharedMemorySize, SMEM_BYTES);

    const int total4 = N * (CCH / 4);
    const int total32 = N * 32;
    const float invN = 1.0f / (float)N;

    // launches: ms(0) ms(1) pack(2) shim(3) shim(4) conv1(5) <- ncu -s 5 target
    pack_x<<<592, 512, 0, s>>>(x, xh, total32);
    shim_kernel<<<1, 32, 0, s>>>(part1);
    shim_kernel<<<1, 32, 0, s>>>(part2);

    // conv1 -> BN1 partials -> fused BN+ReLU+fp16 pack
    conv_tc<<<GRID, 512, SMEM_BYTES, s>>>(xh, w1, idx_in, idx_out, tmp1, M, SMT, TT, PER);
    bn_stats<<<148, 512, 0, s>>>(tmp1, N, part1);
    bn_apply<<<592, 512, 0, s>>>(tmp1, part1, gamma1, beta1, t1h, total32, invN);

    // conv2 -> BN2 partials -> fused residual epilogue
    conv_tc<<<GRID, 512, SMEM_BYTES, s>>>(t1h, w2, idx_in, idx_out, tmp2, M, SMT, TT, PER);
    bn_stats<<<148, 512, 0, s>>>(tmp2, N, part2);
    final_kernel<<<592, 512, 0, s>>>(tmp2, x, part2, gamma2, beta2, out, total4, invN);
}

// round 14
// speedup vs baseline: 1.4980x; 1.4980x over previous
#include <cuda_runtime.h>
#include <cuda_fp16.h>
#include <cstdint>

// Problem shape (dataset-fixed): N=100000 voxels, C=128, K=27 offsets, M=50000 pairs.
#define CCH 128
#define MAXELEM (100000 * 128)

__device__ float    d_tmp[2 * MAXELEM];   // conv1 / conv2 raw fp32 outputs
__device__ uint32_t d_xh[MAXELEM / 2];    // fp16-packed x (conv1 input)
__device__ uint32_t d_t1h[MAXELEM / 2];   // fp16-packed relu(bn1(tmp1)) (conv2 input)
__device__ float    d_part1[148 * 256];
__device__ float    d_part2[148 * 256];

// ---------------- smem layout (bytes) ----------------
// A tiles: 4 buffers (2 per half) of 64 rows x 136 halves (272B/row).
// W tile: 128 couts x 136 halves. idx rings: 2 halves x 8 slots x 128 ints.
#define AROW_B    272
#define A_TILE_B  (64 * AROW_B)             // 17408
#define W_OFF_B   (4 * A_TILE_B)            // 69632
#define W_TILE_B  (128 * AROW_B)            // 34816
#define IDX_OFF_B (W_OFF_B + W_TILE_B)      // 104448
#define SMEM_BYTES (IDX_OFF_B + 2 * 8 * 128 * 4)   // 112640

// ---------------- helpers ----------------
__device__ __forceinline__ uint32_t s2u(const void* p) {
    uint32_t a;
    asm("{ .reg .u64 t; cvta.to.shared.u64 t, %1; cvt.u32.u64 %0, t; }" : "=r"(a) : "l"(p));
    return a;
}
__device__ __forceinline__ void barh(int id) {
    asm volatile("bar.sync %0, 256;" :: "r"(id) : "memory");
}
__device__ __forceinline__ void mma_f16(float* d, uint32_t a0, uint32_t a1, uint32_t a2,
                                        uint32_t a3, uint32_t b0, uint32_t b1) {
    asm volatile(
        "mma.sync.aligned.m16n8k16.row.col.f32.f16.f16.f32 "
        "{%0,%1,%2,%3}, {%4,%5,%6,%7}, {%8,%9}, {%0,%1,%2,%3};"
        : "+f"(d[0]), "+f"(d[1]), "+f"(d[2]), "+f"(d[3])
        : "r"(a0), "r"(a1), "r"(a2), "r"(a3), "r"(b0), "r"(b1));
}
__device__ __forceinline__ void red4(float* p, float a, float b, float c, float d) {
    asm volatile("red.global.add.v4.f32 [%0], {%1,%2,%3,%4};"
                 :: "l"(p), "f"(a), "f"(b), "f"(c), "f"(d) : "memory");
}
__device__ __forceinline__ void cpa16(uint32_t dst, const void* src, int sbytes) {
    asm volatile("cp.async.cg.shared.global [%0], [%1], 16, %2;"
                 :: "r"(dst), "l"(src), "r"(sbytes) : "memory");
}
__device__ __forceinline__ uint32_t pack2(float a, float b) {
    __half2 h = __floats2half2_rn(a, b);
    return *reinterpret_cast<uint32_t*>(&h);
}

// ---------------------------------------------------------------------------
// persistent fused conv, fp16-operand edition (R12 structure — best known):
// 512 threads = 2 independent 256-thread halves (named barriers, own idx ring,
// double-buffered 64-row fp16 A tiles via cp.async). W converted to fp16 in
// smem per k-offset. mma.m16n8k16 f16xf16->f32. Register-direct red.global.v4
// scatter, lane-balanced.
// ---------------------------------------------------------------------------
__global__ __launch_bounds__(512, 1)
void conv_tc(const uint32_t* __restrict__ xh, const float* __restrict__ w,
             const int* __restrict__ idx_in, const int* __restrict__ idx_out,
             float* __restrict__ out, int M, int SMT, int TT, int PER)
{
    extern __shared__ __align__(16) char smc[];
    uint32_t* Ww  = (uint32_t*)(smc + W_OFF_B);   // W word view (2 halves/word)
    __half*   Wh  = (__half*)(smc + W_OFF_B);
    int*      Ism = (int*)(smc + IDX_OFF_B);
    const int tid = threadIdx.x, lane = tid & 31, warp = tid >> 5;
    const int half = warp >> 3;
    const int hwarp = warp & 7;
    const int htid = tid & 255;
    const int barid = 1 + half;

    int t0 = blockIdx.x * PER;
    int t1 = t0 + PER; if (t1 > TT) t1 = TT;
    if (t0 >= t1) return;

    char* Ah = smc + half * (2 * A_TILE_B);
    int*  Ih = Ism + half * (8 * 128);
    const uint32_t ahu = s2u(Ah);
    const uint32_t ihu = s2u(Ih);

    // synchronous preload of idx for t0, t0+1 (this half's 64 rows)
    for (int t = t0; t < t0 + 2 && t < t1; t++) {
        int k = t / SMT, smt = t - k * SMT, m0 = smt * 128 + half * 64;
        int nr = M - m0; if (nr > 64) nr = 64; if (nr < 0) nr = 0;
        int* slot = Ih + (t & 7) * 128;
        if (htid < 64)       slot[htid] = (htid < nr) ? __ldg(idx_in + (size_t)k * M + m0 + htid) : 0;
        else if (htid < 128) slot[htid] = ((htid - 64) < nr) ? __ldg(idx_out + (size_t)k * M + m0 + (htid - 64)) : 0;
    }
    __syncthreads();

    // gather this half's 64 fp16 rows (256B each = 16 chunks) + idx prefetch t+2
    auto issue_gather = [&](int t) {
        int k = t / SMT, smt = t - k * SMT, m0 = smt * 128 + half * 64;
        int nr = M - m0; if (nr > 64) nr = 64; if (nr < 0) nr = 0;
        const int* slot = Ih + (t & 7) * 128;
        uint32_t ab = ahu + (uint32_t)(t & 1) * A_TILE_B;
        #pragma unroll
        for (int j = 0; j < 4; j++) {
            int id = htid + j * 256;
            int row = id >> 4, s = id & 15;
            int ok = (row < nr);
            int src = ok ? slot[row] : 0;
            cpa16(ab + (uint32_t)(row * AROW_B + s * 16),
                  (const char*)xh + (size_t)src * 256 + s * 16, ok ? 16 : 0);
        }
        int tn = t + 2;
        if (tn < t1 && htid < 32) {
            int k2 = tn / SMT, smt2 = tn - k2 * SMT, m02 = smt2 * 128 + half * 64;
            int nr2 = M - m02; if (nr2 > 64) nr2 = 64; if (nr2 < 0) nr2 = 0;
            int r = (htid & 15) * 4;
            const int* g = (htid < 16) ? (idx_in  + (size_t)k2 * M + m02)
                                       : (idx_out + (size_t)k2 * M + m02);
            uint32_t sdst = ihu + (uint32_t)(((tn & 7) * 128) + ((htid < 16) ? 0 : 64) + r) * 4;
            int nb = (r + 4 <= nr2) ? 16 : ((r < nr2) ? (nr2 - r) * 4 : 0);
            cpa16(sdst, g + r, nb);
        }
        asm volatile("cp.async.commit_group;" ::: "memory");
    };

    issue_gather(t0);
    if (t0 + 1 < t1) issue_gather(t0 + 1);

    int kcur = -1;
    const int wm = hwarp & 1, wn = hwarp >> 1;   // 2x4 warp grid over 64x128
    const int gr = lane >> 2, tg = lane & 3;
    const bool oddlane = (lane & 1);

    for (int i = t0; i < t1; i++) {
        int k = i / SMT, smt = i - k * SMT, m0 = smt * 128 + half * 64;
        int nr = M - m0; if (nr > 64) nr = 64; if (nr < 0) nr = 0;
        const uint32_t* Aw = (const uint32_t*)(Ah + (i & 1) * A_TILE_B);
        const int* slot = Ih + (i & 7) * 128;

        if (i + 1 < t1) asm volatile("cp.async.wait_group 1;" ::: "memory");
        else            asm volatile("cp.async.wait_group 0;" ::: "memory");
        barh(barid);

        if (k != kcur) {                       // rare: both halves at same i
            __syncthreads();
            const float* wk = w + (size_t)k * (CCH * CCH);
            #pragma unroll 4
            for (int j = 0; j < 32; j++) {
                int idx = tid + j * 512;
                int cin = idx >> 7, cout = idx & 127;
                Wh[cout * 136 + cin] = __float2half_rn(wk[idx]);
            }
            kcur = k;
            __syncthreads();
        }

        float acc[2][4][4];
        #pragma unroll
        for (int a = 0; a < 2; a++)
            #pragma unroll
            for (int b = 0; b < 4; b++)
                #pragma unroll
                for (int c = 0; c < 4; c++) acc[a][b][c] = 0.f;

        const int rbase = wm * 32 + gr;        // row word stride = 68

        #pragma unroll
        for (int ks = 0; ks < 8; ks++) {
            uint32_t b0[4], b1[4];
            #pragma unroll
            for (int nf = 0; nf < 4; nf++) {
                int col = wn * 32 + nf * 8 + gr;
                b0[nf] = Ww[col * 68 + ks * 8 + tg];
                b1[nf] = Ww[col * 68 + ks * 8 + tg + 4];
            }
            #pragma unroll
            for (int mf = 0; mf < 2; mf++) {
                int r = rbase + mf * 16;
                uint32_t a0 = Aw[r * 68 + ks * 8 + tg];
                uint32_t a1 = Aw[(r + 8) * 68 + ks * 8 + tg];
                uint32_t a2 = Aw[r * 68 + ks * 8 + tg + 4];
                uint32_t a3 = Aw[(r + 8) * 68 + ks * 8 + tg + 4];
                #pragma unroll
                for (int nf = 0; nf < 4; nf++)
                    mma_f16(acc[mf][nf], a0, a1, a2, a3, b0[nf], b1[nf]);
            }
        }
        barh(barid);                 // this half done reading its A buffer

        if (i + 2 < t1) issue_gather(i + 2);

        // lane-balanced register-direct scatter
        const int* oslot = slot + 64;
        #pragma unroll
        for (int mf = 0; mf < 2; mf++) {
            #pragma unroll
            for (int rh = 0; rh < 2; rh++) {
                int r = wm * 32 + mf * 16 + rh * 8 + gr;
                int dst = (r < nr) ? oslot[r] : -1;
                #pragma unroll
                for (int nf = 0; nf < 4; nf++) {
                    float c0 = acc[mf][nf][rh * 2 + 0];
                    float c1 = acc[mf][nf][rh * 2 + 1];
                    float q0 = __shfl_xor_sync(0xFFFFFFFFu, c0, 1);
                    float q1 = __shfl_xor_sync(0xFFFFFFFFu, c1, 1);
                    bool mine = (((nf & 1) ^ (lane & 1)) == 0);
                    if (mine && dst >= 0) {
                        float a0 = oddlane ? q0 : c0, a1 = oddlane ? q1 : c1;
                        float a2 = oddlane ? c0 : q0, a3 = oddlane ? c1 : q1;
                        int col = wn * 32 + nf * 8 + (tg & 2) * 2;
                        red4(out + (size_t)dst * CCH + col, a0, a1, a2, a3);
                    }
                }
            }
        }
    }
}

// ---------------- tiny shim kernels (profiling alignment, ~1us each) -------
__global__ void shim_kernel(float* p) { if (threadIdx.x == 1023) p[0] = 0.f; }

// ---------------- pack x -> fp16 ----------------
__global__ __launch_bounds__(512)
void pack_x(const float* __restrict__ x, uint32_t* __restrict__ xh, int total32)
{
    const int stride = gridDim.x * blockDim.x;
    for (int i = blockIdx.x * blockDim.x + threadIdx.x; i < total32; i += 2 * stride) {
        int i2 = i + stride;
        float4 v = reinterpret_cast<const float4*>(x)[i];
        float4 u = (i2 < total32) ? reinterpret_cast<const float4*>(x)[i2]
                                  : make_float4(0.f, 0.f, 0.f, 0.f);
        reinterpret_cast<uint2*>(xh)[i] = make_uint2(pack2(v.x, v.y), pack2(v.z, v.w));
        if (i2 < total32)
            reinterpret_cast<uint2*>(xh)[i2] = make_uint2(pack2(u.x, u.y), pack2(u.z, u.w));
    }
}

// ---------------- BN stats: vectorized float4, per-block partials ----------
__global__ __launch_bounds__(512)
void bn_stats(const float* __restrict__ t, int N, float* __restrict__ part)
{
    __shared__ float sh[16 * 128], sh2[16 * 128];
    const int cg = threadIdx.x & 31;
    const int rs = threadIdx.x >> 5;
    float4 s  = make_float4(0.f, 0.f, 0.f, 0.f);
    float4 s2 = make_float4(0.f, 0.f, 0.f, 0.f);
    for (int r = blockIdx.x * 16 + rs; r < N; r += gridDim.x * 16) {
        float4 v = reinterpret_cast<const float4*>(t)[(size_t)r * 32 + cg];
        s.x += v.x; s.y += v.y; s.z += v.z; s.w += v.w;
        s2.x = fmaf(v.x, v.x, s2.x); s2.y = fmaf(v.y, v.y, s2.y);
        s2.z = fmaf(v.z, v.z, s2.z); s2.w = fmaf(v.w, v.w, s2.w);
    }
    reinterpret_cast<float4*>(sh)[rs * 32 + cg]  = s;
    reinterpret_cast<float4*>(sh2)[rs * 32 + cg] = s2;
    __syncthreads();
    if (threadIdx.x < 128) {
        int c = threadIdx.x;
        float ss = 0.f, ss2 = 0.f;
        #pragma unroll
        for (int j = 0; j < 16; j++) {
            ss  += sh[j * 128 + c];
            ss2 += sh2[j * 128 + c];
        }
        part[blockIdx.x * 256 + c]       = ss;
        part[blockIdx.x * 256 + 128 + c] = ss2;
    }
}

__device__ __forceinline__ void make_sb(const float* __restrict__ part,
                                        const float* __restrict__ gamma,
                                        const float* __restrict__ beta,
                                        float invN, float* sb)
{
    if (threadIdx.x < 128) {
        int c = threadIdx.x;
        float s = 0.f, s2 = 0.f;
        #pragma unroll 4
        for (int b = 0; b < 148; b++) {
            s  += part[b * 256 + c];
            s2 += part[b * 256 + 128 + c];
        }
        float mean = s * invN;
        float var  = s2 * invN - mean * mean;
        float sc   = gamma[c] * rsqrtf(var + 1e-5f);
        sb[c]       = sc;
        sb[128 + c] = beta[c] - mean * sc;
    }
    __syncthreads();
}

// bn1 + relu -> fp16 packed (conv2 input)
__global__ __launch_bounds__(512)
void bn_apply(const float* __restrict__ t, const float* __restrict__ part,
              const float* __restrict__ gamma, const float* __restrict__ beta,
              uint32_t* __restrict__ o, int total32, float invN)
{
    __shared__ float sb[256];
    make_sb(part, gamma, beta, invN, sb);
    const int stride = gridDim.x * blockDim.x;
    for (int i = blockIdx.x * blockDim.x + threadIdx.x; i < total32; i += 2 * stride) {
        int i2 = i + stride;
        float4 v = reinterpret_cast<const float4*>(t)[i];
        float4 u = (i2 < total32) ? reinterpret_cast<const float4*>(t)[i2]
                                  : make_float4(0.f, 0.f, 0.f, 0.f);
        int c = (i & 31) * 4;
        v.x = fmaxf(fmaf(v.x, sb[c + 0], sb[128 + c + 0]), 0.f);
        v.y = fmaxf(fmaf(v.y, sb[c + 1], sb[128 + c + 1]), 0.f);
        v.z = fmaxf(fmaf(v.z, sb[c + 2], sb[128 + c + 2]), 0.f);
        v.w = fmaxf(fmaf(v.w, sb[c + 3], sb[128 + c + 3]), 0.f);
        reinterpret_cast<uint2*>(o)[i] = make_uint2(pack2(v.x, v.y), pack2(v.z, v.w));
        if (i2 < total32) {
            int c2 = (i2 & 31) * 4;
            u.x = fmaxf(fmaf(u.x, sb[c2 + 0], sb[128 + c2 + 0]), 0.f);
            u.y = fmaxf(fmaf(u.y, sb[c2 + 1], sb[128 + c2 + 1]), 0.f);
            u.z = fmaxf(fmaf(u.z, sb[c2 + 2], sb[128 + c2 + 2]), 0.f);
            u.w = fmaxf(fmaf(u.w, sb[c2 + 3], sb[128 + c2 + 3]), 0.f);
            reinterpret_cast<uint2*>(o)[i2] = make_uint2(pack2(u.x, u.y), pack2(u.z, u.w));
        }
    }
}

// out = relu(bn2(conv2) + identity)
__global__ __launch_bounds__(512)
void final_kernel(const float* __restrict__ t2, const float* __restrict__ x,
                  const float* __restrict__ part,
                  const float* __restrict__ gamma, const float* __restrict__ beta,
                  float* __restrict__ out, int total4, float invN)
{
    __shared__ float sb[256];
    make_sb(part, gamma, beta, invN, sb);
    const int stride = gridDim.x * blockDim.x;
    for (int i = blockIdx.x * blockDim.x + threadIdx.x; i < total4; i += 2 * stride) {
        int i2 = i + stride;
        float4 v  = reinterpret_cast<const float4*>(t2)[i];
        float4 xi = reinterpret_cast<const float4*>(x)[i];
        int c = (i & 31) * 4;
        float4 o;
        o.x = fmaxf(fmaf(v.x, sb[c + 0], sb[128 + c + 0]) + xi.x, 0.f);
        o.y = fmaxf(fmaf(v.y, sb[c + 1], sb[128 + c + 1]) + xi.y, 0.f);
        o.z = fmaxf(fmaf(v.z, sb[c + 2], sb[128 + c + 2]) + xi.z, 0.f);
        o.w = fmaxf(fmaf(v.w, sb[c + 3], sb[128 + c + 3]) + xi.w, 0.f);
        reinterpret_cast<float4*>(out)[i] = o;
        if (i2 < total4) {
            float4 v2 = reinterpret_cast<const float4*>(t2)[i2];
            float4 x2 = reinterpret_cast<const float4*>(x)[i2];
            int c2 = (i2 & 31) * 4;
            float4 o2;
            o2.x = fmaxf(fmaf(v2.x, sb[c2 + 0], sb[128 + c2 + 0]) + x2.x, 0.f);
            o2.y = fmaxf(fmaf(v2.y, sb[c2 + 1], sb[128 + c2 + 1]) + x2.y, 0.f);
            o2.z = fmaxf(fmaf(v2.z, sb[c2 + 2], sb[128 + c2 + 2]) + x2.z, 0.f);
            o2.w = fmaxf(fmaf(v2.w, sb[c2 + 3], sb[128 + c2 + 3]) + x2.w, 0.f);
            reinterpret_cast<float4*>(out)[i2] = o2;
        }
    }
}

// ---------------- launch ----------------
extern "C" void kernel_launch(void* const* d_in, const int* in_sizes, int n_in,
                              void* d_out, int out_size)
{
    const float* x      = (const float*)d_in[0];
    const float* w1     = (const float*)d_in[1];
    const float* gamma1 = (const float*)d_in[2];
    const float* beta1  = (const float*)d_in[3];
    const float* w2     = (const float*)d_in[4];
    const float* gamma2 = (const float*)d_in[5];
    const float* beta2  = (const float*)d_in[6];
    const int*   idx_in  = (const int*)d_in[7];
    const int*   idx_out = (const int*)d_in[8];
    float* out = (float*)d_out;

    const int N = in_sizes[0] / CCH;           // 100000
    const int K = in_sizes[1] / (CCH * CCH);   // 27
    const int M = in_sizes[7] / K;             // 50000
    const int SMT = (M + 127) / 128;           // 128-row super-tiles per offset
    const int TT = K * SMT;                    // total super-tiles
    const int GRID = 148;
    const int PER = (TT + GRID - 1) / GRID;

    cudaStream_t s = 0;

    float *tmp, *part1, *part2;
    uint32_t *xh, *t1h;
    cudaGetSymbolAddress((void**)&tmp,   d_tmp);
    cudaGetSymbolAddress((void**)&xh,    d_xh);
    cudaGetSymbolAddress((void**)&t1h,   d_t1h);
    cudaGetSymbolAddress((void**)&part1, d_part1);
    cudaGetSymbolAddress((void**)&part2, d_part2);
    float* tmp1 = tmp;
    float* tmp2 = tmp + (size_t)MAXELEM;

    size_t nb = (size_t)N * CCH * sizeof(float);
    cudaMemsetAsync(tmp1, 0, 2 * nb, s);       // splits into 2 launches (>64MB)

    cudaFuncSetAttribute(conv_tc, cudaFuncAttributeMaxDynamicSharedMemorySize, SMEM_BYTES);

    const int total4 = N * (CCH / 4);
    const int total32 = N * 32;
    const float invN = 1.0f / (float)N;

    // launches: ms(0) ms(1) pack(2) shim(3) shim(4) conv1(5) <- ncu -s 5 target
    pack_x<<<592, 512, 0, s>>>(x, xh, total32);
    shim_kernel<<<1, 32, 0, s>>>(part1);
    shim_kernel<<<1, 32, 0, s>>>(part2);

    // conv1 -> BN1 partials -> fused BN+ReLU+fp16 pack
    conv_tc<<<GRID, 512, SMEM_BYTES, s>>>(xh, w1, idx_in, idx_out, tmp1, M, SMT, TT, PER);
    bn_stats<<<148, 512, 0, s>>>(tmp1, N, part1);
    bn_apply<<<592, 512, 0, s>>>(tmp1, part1, gamma1, beta1, t1h, total32, invN);

    // conv2 -> BN2 partials -> fused residual epilogue
    conv_tc<<<GRID, 512, SMEM_BYTES, s>>>(t1h, w2, idx_in, idx_out, tmp2, M, SMT, TT, PER);
    bn_stats<<<148, 512, 0, s>>>(tmp2, N, part2);
    final_kernel<<<592, 512, 0, s>>>(tmp2, x, part2, gamma2, beta2, out, total4, invN);
}

// round 15
// speedup vs baseline: 1.5495x; 1.0344x over previous
#include <cuda_runtime.h>
#include <cuda_fp16.h>
#include <cstdint>

// Problem shape (dataset-fixed): N=100000 voxels, C=128, K=27 offsets, M=50000 pairs.
#define CCH 128
#define MAXELEM (100000 * 128)

__device__ float    d_tmp[2 * MAXELEM];   // conv1 / conv2 raw fp32 outputs
__device__ uint32_t d_xh[MAXELEM / 2];    // fp16-packed x (conv1 input)
__device__ uint32_t d_t1h[MAXELEM / 2];   // fp16-packed relu(bn1(tmp1)) (conv2 input)
__device__ float    d_part1[148 * 256];
__device__ float    d_part2[148 * 256];

// ---------------- smem layout (bytes) ----------------
// A tiles: 4 buffers (2 per half) of 64 rows x 136 halves (272B/row).
// W tile: 128 couts x 136 halves. idx rings: 2 halves x 8 slots x 128 ints.
#define AROW_B    272
#define A_TILE_B  (64 * AROW_B)             // 17408
#define W_OFF_B   (4 * A_TILE_B)            // 69632
#define W_TILE_B  (128 * AROW_B)            // 34816
#define IDX_OFF_B (W_OFF_B + W_TILE_B)      // 104448
#define SMEM_BYTES (IDX_OFF_B + 2 * 8 * 128 * 4)   // 112640

// ---------------- helpers ----------------
__device__ __forceinline__ uint32_t s2u(const void* p) {
    uint32_t a;
    asm("{ .reg .u64 t; cvta.to.shared.u64 t, %1; cvt.u32.u64 %0, t; }" : "=r"(a) : "l"(p));
    return a;
}
__device__ __forceinline__ void barh(int id) {
    asm volatile("bar.sync %0, 256;" :: "r"(id) : "memory");
}
__device__ __forceinline__ void mma_f16(float* d, uint32_t a0, uint32_t a1, uint32_t a2,
                                        uint32_t a3, uint32_t b0, uint32_t b1) {
    asm volatile(
        "mma.sync.aligned.m16n8k16.row.col.f32.f16.f16.f32 "
        "{%0,%1,%2,%3}, {%4,%5,%6,%7}, {%8,%9}, {%0,%1,%2,%3};"
        : "+f"(d[0]), "+f"(d[1]), "+f"(d[2]), "+f"(d[3])
        : "r"(a0), "r"(a1), "r"(a2), "r"(a3), "r"(b0), "r"(b1));
}
__device__ __forceinline__ void ldsm4(uint32_t& r0, uint32_t& r1, uint32_t& r2, uint32_t& r3,
                                      uint32_t addr) {
    asm volatile("ldmatrix.sync.aligned.m8n8.x4.shared.b16 {%0,%1,%2,%3}, [%4];"
                 : "=r"(r0), "=r"(r1), "=r"(r2), "=r"(r3) : "r"(addr));
}
__device__ __forceinline__ void red4(float* p, float a, float b, float c, float d) {
    asm volatile("red.global.add.v4.f32 [%0], {%1,%2,%3,%4};"
                 :: "l"(p), "f"(a), "f"(b), "f"(c), "f"(d) : "memory");
}
__device__ __forceinline__ void cpa16(uint32_t dst, const void* src, int sbytes) {
    asm volatile("cp.async.cg.shared.global [%0], [%1], 16, %2;"
                 :: "r"(dst), "l"(src), "r"(sbytes) : "memory");
}
__device__ __forceinline__ uint32_t pack2(float a, float b) {
    __half2 h = __floats2half2_rn(a, b);
    return *reinterpret_cast<uint32_t*>(&h);
}

// ---------------------------------------------------------------------------
// persistent fused conv, fp16 + ldmatrix edition:
// Identical pipeline to the 712us kernel; only the fragment loads change:
// 32 ldmatrix.m8n8.x4 per warp-tile replace 128 scalar LDS.32.
// ---------------------------------------------------------------------------
__global__ __launch_bounds__(512, 1)
void conv_tc(const uint32_t* __restrict__ xh, const float* __restrict__ w,
             const int* __restrict__ idx_in, const int* __restrict__ idx_out,
             float* __restrict__ out, int M, int SMT, int TT, int PER)
{
    extern __shared__ __align__(16) char smc[];
    __half* Wh  = (__half*)(smc + W_OFF_B);
    int*    Ism = (int*)(smc + IDX_OFF_B);
    const int tid = threadIdx.x, lane = tid & 31, warp = tid >> 5;
    const int half = warp >> 3;
    const int hwarp = warp & 7;
    const int htid = tid & 255;
    const int barid = 1 + half;

    int t0 = blockIdx.x * PER;
    int t1 = t0 + PER; if (t1 > TT) t1 = TT;
    if (t0 >= t1) return;

    char* Ah = smc + half * (2 * A_TILE_B);
    int*  Ih = Ism + half * (8 * 128);
    const uint32_t ahu = s2u(Ah);
    const uint32_t ihu = s2u(Ih);

    // synchronous preload of idx for t0, t0+1 (this half's 64 rows)
    for (int t = t0; t < t0 + 2 && t < t1; t++) {
        int k = t / SMT, smt = t - k * SMT, m0 = smt * 128 + half * 64;
        int nr = M - m0; if (nr > 64) nr = 64; if (nr < 0) nr = 0;
        int* slot = Ih + (t & 7) * 128;
        if (htid < 64)       slot[htid] = (htid < nr) ? __ldg(idx_in + (size_t)k * M + m0 + htid) : 0;
        else if (htid < 128) slot[htid] = ((htid - 64) < nr) ? __ldg(idx_out + (size_t)k * M + m0 + (htid - 64)) : 0;
    }
    __syncthreads();

    // gather this half's 64 fp16 rows (256B each = 16 chunks) + idx prefetch t+2
    auto issue_gather = [&](int t) {
        int k = t / SMT, smt = t - k * SMT, m0 = smt * 128 + half * 64;
        int nr = M - m0; if (nr > 64) nr = 64; if (nr < 0) nr = 0;
        const int* slot = Ih + (t & 7) * 128;
        uint32_t ab = ahu + (uint32_t)(t & 1) * A_TILE_B;
        #pragma unroll
        for (int j = 0; j < 4; j++) {
            int id = htid + j * 256;
            int row = id >> 4, s = id & 15;
            int ok = (row < nr);
            int src = ok ? slot[row] : 0;
            cpa16(ab + (uint32_t)(row * AROW_B + s * 16),
                  (const char*)xh + (size_t)src * 256 + s * 16, ok ? 16 : 0);
        }
        int tn = t + 2;
        if (tn < t1 && htid < 32) {
            int k2 = tn / SMT, smt2 = tn - k2 * SMT, m02 = smt2 * 128 + half * 64;
            int nr2 = M - m02; if (nr2 > 64) nr2 = 64; if (nr2 < 0) nr2 = 0;
            int r = (htid & 15) * 4;
            const int* g = (htid < 16) ? (idx_in  + (size_t)k2 * M + m02)
                                       : (idx_out + (size_t)k2 * M + m02);
            uint32_t sdst = ihu + (uint32_t)(((tn & 7) * 128) + ((htid < 16) ? 0 : 64) + r) * 4;
            int nb = (r + 4 <= nr2) ? 16 : ((r < nr2) ? (nr2 - r) * 4 : 0);
            cpa16(sdst, g + r, nb);
        }
        asm volatile("cp.async.commit_group;" ::: "memory");
    };

    issue_gather(t0);
    if (t0 + 1 < t1) issue_gather(t0 + 1);

    int kcur = -1;
    const int wm = hwarp & 1, wn = hwarp >> 1;   // 2x4 warp grid over 64x128
    const int gr = lane >> 2, tg = lane & 3;
    const bool oddlane = (lane & 1);

    // ldmatrix per-lane base addresses (byte offsets), loop-invariant:
    // A x4: lane l -> row (l&15) (+mf*16), k-16B-group (l>>4)
    const uint32_t aoff = (uint32_t)((wm * 32 + (lane & 15)) * AROW_B + (lane >> 4) * 16);
    // B x4: lane l -> matrix m=l>>3: col (m>>1)*8+(l&7) (+nfp*16), k-16B-group m&1
    const uint32_t wsu = s2u(smc + W_OFF_B);
    const int bm = lane >> 3;
    const uint32_t bb0 = wsu + (uint32_t)((wn * 32 + (bm >> 1) * 8 + (lane & 7)) * AROW_B
                                          + (bm & 1) * 16);
    const uint32_t bb1 = bb0 + 16 * AROW_B;

    for (int i = t0; i < t1; i++) {
        int k = i / SMT, smt = i - k * SMT, m0 = smt * 128 + half * 64;
        int nr = M - m0; if (nr > 64) nr = 64; if (nr < 0) nr = 0;
        const int* slot = Ih + (i & 7) * 128;
        const uint32_t abase = ahu + (uint32_t)(i & 1) * A_TILE_B + aoff;

        if (i + 1 < t1) asm volatile("cp.async.wait_group 1;" ::: "memory");
        else            asm volatile("cp.async.wait_group 0;" ::: "memory");
        barh(barid);

        if (k != kcur) {                       // rare: both halves at same i
            __syncthreads();
            const float* wk = w + (size_t)k * (CCH * CCH);
            #pragma unroll 4
            for (int j = 0; j < 32; j++) {
                int idx = tid + j * 512;
                int cin = idx >> 7, cout = idx & 127;
                Wh[cout * 136 + cin] = __float2half_rn(wk[idx]);
            }
            kcur = k;
            __syncthreads();
        }

        float acc[2][4][4];
        #pragma unroll
        for (int a = 0; a < 2; a++)
            #pragma unroll
            for (int b = 0; b < 4; b++)
                #pragma unroll
                for (int c = 0; c < 4; c++) acc[a][b][c] = 0.f;

        #pragma unroll
        for (int ks = 0; ks < 8; ks++) {
            uint32_t b0[4], b1[4];
            ldsm4(b0[0], b1[0], b0[1], b1[1], bb0 + ks * 32);
            ldsm4(b0[2], b1[2], b0[3], b1[3], bb1 + ks * 32);
            uint32_t a[2][4];
            ldsm4(a[0][0], a[0][1], a[0][2], a[0][3], abase + ks * 32);
            ldsm4(a[1][0], a[1][1], a[1][2], a[1][3], abase + 16 * AROW_B + ks * 32);
            #pragma unroll
            for (int mf = 0; mf < 2; mf++)
                #pragma unroll
                for (int nf = 0; nf < 4; nf++)
                    mma_f16(acc[mf][nf], a[mf][0], a[mf][1], a[mf][2], a[mf][3],
                            b0[nf], b1[nf]);
        }
        barh(barid);                 // this half done reading its A buffer

        if (i + 2 < t1) issue_gather(i + 2);

        // lane-balanced register-direct scatter
        const int* oslot = slot + 64;
        #pragma unroll
        for (int mf = 0; mf < 2; mf++) {
            #pragma unroll
            for (int rh = 0; rh < 2; rh++) {
                int r = wm * 32 + mf * 16 + rh * 8 + gr;
                int dst = (r < nr) ? oslot[r] : -1;
                #pragma unroll
                for (int nf = 0; nf < 4; nf++) {
                    float c0 = acc[mf][nf][rh * 2 + 0];
                    float c1 = acc[mf][nf][rh * 2 + 1];
                    float q0 = __shfl_xor_sync(0xFFFFFFFFu, c0, 1);
                    float q1 = __shfl_xor_sync(0xFFFFFFFFu, c1, 1);
                    bool mine = (((nf & 1) ^ (lane & 1)) == 0);
                    if (mine && dst >= 0) {
                        float a0 = oddlane ? q0 : c0, a1 = oddlane ? q1 : c1;
                        float a2 = oddlane ? c0 : q0, a3 = oddlane ? c1 : q1;
                        int col = wn * 32 + nf * 8 + (tg & 2) * 2;
                        red4(out + (size_t)dst * CCH + col, a0, a1, a2, a3);
                    }
                }
            }
        }
    }
}

// ---------------- tiny shim kernels (profiling alignment, ~1us each) -------
__global__ void shim_kernel(float* p) { if (threadIdx.x == 1023) p[0] = 0.f; }

// ---------------- pack x -> fp16 ----------------
__global__ __launch_bounds__(512)
void pack_x(const float* __restrict__ x, uint32_t* __restrict__ xh, int total32)
{
    const int stride = gridDim.x * blockDim.x;
    for (int i = blockIdx.x * blockDim.x + threadIdx.x; i < total32; i += 2 * stride) {
        int i2 = i + stride;
        float4 v = reinterpret_cast<const float4*>(x)[i];
        float4 u = (i2 < total32) ? reinterpret_cast<const float4*>(x)[i2]
                                  : make_float4(0.f, 0.f, 0.f, 0.f);
        reinterpret_cast<uint2*>(xh)[i] = make_uint2(pack2(v.x, v.y), pack2(v.z, v.w));
        if (i2 < total32)
            reinterpret_cast<uint2*>(xh)[i2] = make_uint2(pack2(u.x, u.y), pack2(u.z, u.w));
    }
}

// ---------------- BN stats: vectorized float4, per-block partials ----------
__global__ __launch_bounds__(512)
void bn_stats(const float* __restrict__ t, int N, float* __restrict__ part)
{
    __shared__ float sh[16 * 128], sh2[16 * 128];
    const int cg = threadIdx.x & 31;
    const int rs = threadIdx.x >> 5;
    float4 s  = make_float4(0.f, 0.f, 0.f, 0.f);
    float4 s2 = make_float4(0.f, 0.f, 0.f, 0.f);
    for (int r = blockIdx.x * 16 + rs; r < N; r += gridDim.x * 16) {
        float4 v = reinterpret_cast<const float4*>(t)[(size_t)r * 32 + cg];
        s.x += v.x; s.y += v.y; s.z += v.z; s.w += v.w;
        s2.x = fmaf(v.x, v.x, s2.x); s2.y = fmaf(v.y, v.y, s2.y);
        s2.z = fmaf(v.z, v.z, s2.z); s2.w = fmaf(v.w, v.w, s2.w);
    }
    reinterpret_cast<float4*>(sh)[rs * 32 + cg]  = s;
    reinterpret_cast<float4*>(sh2)[rs * 32 + cg] = s2;
    __syncthreads();
    if (threadIdx.x < 128) {
        int c = threadIdx.x;
        float ss = 0.f, ss2 = 0.f;
        #pragma unroll
        for (int j = 0; j < 16; j++) {
            ss  += sh[j * 128 + c];
            ss2 += sh2[j * 128 + c];
        }
        part[blockIdx.x * 256 + c]       = ss;
        part[blockIdx.x * 256 + 128 + c] = ss2;
    }
}

__device__ __forceinline__ void make_sb(const float* __restrict__ part,
                                        const float* __restrict__ gamma,
                                        const float* __restrict__ beta,
                                        float invN, float* sb)
{
    if (threadIdx.x < 128) {
        int c = threadIdx.x;
        float s = 0.f, s2 = 0.f;
        #pragma unroll 4
        for (int b = 0; b < 148; b++) {
            s  += part[b * 256 + c];
            s2 += part[b * 256 + 128 + c];
        }
        float mean = s * invN;
        float var  = s2 * invN - mean * mean;
        float sc   = gamma[c] * rsqrtf(var + 1e-5f);
        sb[c]       = sc;
        sb[128 + c] = beta[c] - mean * sc;
    }
    __syncthreads();
}

// bn1 + relu -> fp16 packed (conv2 input)
__global__ __launch_bounds__(512)
void bn_apply(const float* __restrict__ t, const float* __restrict__ part,
              const float* __restrict__ gamma, const float* __restrict__ beta,
              uint32_t* __restrict__ o, int total32, float invN)
{
    __shared__ float sb[256];
    make_sb(part, gamma, beta, invN, sb);
    const int stride = gridDim.x * blockDim.x;
    for (int i = blockIdx.x * blockDim.x + threadIdx.x; i < total32; i += 2 * stride) {
        int i2 = i + stride;
        float4 v = reinterpret_cast<const float4*>(t)[i];
        float4 u = (i2 < total32) ? reinterpret_cast<const float4*>(t)[i2]
                                  : make_float4(0.f, 0.f, 0.f, 0.f);
        int c = (i & 31) * 4;
        v.x = fmaxf(fmaf(v.x, sb[c + 0], sb[128 + c + 0]), 0.f);
        v.y = fmaxf(fmaf(v.y, sb[c + 1], sb[128 + c + 1]), 0.f);
        v.z = fmaxf(fmaf(v.z, sb[c + 2], sb[128 + c + 2]), 0.f);
        v.w = fmaxf(fmaf(v.w, sb[c + 3], sb[128 + c + 3]), 0.f);
        reinterpret_cast<uint2*>(o)[i] = make_uint2(pack2(v.x, v.y), pack2(v.z, v.w));
        if (i2 < total32) {
            int c2 = (i2 & 31) * 4;
            u.x = fmaxf(fmaf(u.x, sb[c2 + 0], sb[128 + c2 + 0]), 0.f);
            u.y = fmaxf(fmaf(u.y, sb[c2 + 1], sb[128 + c2 + 1]), 0.f);
            u.z = fmaxf(fmaf(u.z, sb[c2 + 2], sb[128 + c2 + 2]), 0.f);
            u.w = fmaxf(fmaf(u.w, sb[c2 + 3], sb[128 + c2 + 3]), 0.f);
            reinterpret_cast<uint2*>(o)[i2] = make_uint2(pack2(u.x, u.y), pack2(u.z, u.w));
        }
    }
}

// out = relu(bn2(conv2) + identity)
__global__ __launch_bounds__(512)
void final_kernel(const float* __restrict__ t2, const float* __restrict__ x,
                  const float* __restrict__ part,
                  const float* __restrict__ gamma, const float* __restrict__ beta,
                  float* __restrict__ out, int total4, float invN)
{
    __shared__ float sb[256];
    make_sb(part, gamma, beta, invN, sb);
    const int stride = gridDim.x * blockDim.x;
    for (int i = blockIdx.x * blockDim.x + threadIdx.x; i < total4; i += 2 * stride) {
        int i2 = i + stride;
        float4 v  = reinterpret_cast<const float4*>(t2)[i];
        float4 xi = reinterpret_cast<const float4*>(x)[i];
        int c = (i & 31) * 4;
        float4 o;
        o.x = fmaxf(fmaf(v.x, sb[c + 0], sb[128 + c + 0]) + xi.x, 0.f);
        o.y = fmaxf(fmaf(v.y, sb[c + 1], sb[128 + c + 1]) + xi.y, 0.f);
        o.z = fmaxf(fmaf(v.z, sb[c + 2], sb[128 + c + 2]) + xi.z, 0.f);
        o.w = fmaxf(fmaf(v.w, sb[c + 3], sb[128 + c + 3]) + xi.w, 0.f);
        reinterpret_cast<float4*>(out)[i] = o;
        if (i2 < total4) {
            float4 v2 = reinterpret_cast<const float4*>(t2)[i2];
            float4 x2 = reinterpret_cast<const float4*>(x)[i2];
            int c2 = (i2 & 31) * 4;
            float4 o2;
            o2.x = fmaxf(fmaf(v2.x, sb[c2 + 0], sb[128 + c2 + 0]) + x2.x, 0.f);
            o2.y = fmaxf(fmaf(v2.y, sb[c2 + 1], sb[128 + c2 + 1]) + x2.y, 0.f);
            o2.z = fmaxf(fmaf(v2.z, sb[c2 + 2], sb[128 + c2 + 2]) + x2.z, 0.f);
            o2.w = fmaxf(fmaf(v2.w, sb[c2 + 3], sb[128 + c2 + 3]) + x2.w, 0.f);
            reinterpret_cast<float4*>(out)[i2] = o2;
        }
    }
}

// ---------------- launch ----------------
extern "C" void kernel_launch(void* const* d_in, const int* in_sizes, int n_in,
                              void* d_out, int out_size)
{
    const float* x      = (const float*)d_in[0];
    const float* w1     = (const float*)d_in[1];
    const float* gamma1 = (const float*)d_in[2];
    const float* beta1  = (const float*)d_in[3];
    const float* w2     = (const float*)d_in[4];
    const float* gamma2 = (const float*)d_in[5];
    const float* beta2  = (const float*)d_in[6];
    const int*   idx_in  = (const int*)d_in[7];
    const int*   idx_out = (const int*)d_in[8];
    float* out = (float*)d_out;

    const int N = in_sizes[0] / CCH;           // 100000
    const int K = in_sizes[1] / (CCH * CCH);   // 27
    const int M = in_sizes[7] / K;             // 50000
    const int SMT = (M + 127) / 128;           // 128-row super-tiles per offset
    const int TT = K * SMT;                    // total super-tiles
    const int GRID = 148;
    const int PER = (TT + GRID - 1) / GRID;

    cudaStream_t s = 0;

    float *tmp, *part1, *part2;
    uint32_t *xh, *t1h;
    cudaGetSymbolAddress((void**)&tmp,   d_tmp);
    cudaGetSymbolAddress((void**)&xh,    d_xh);
    cudaGetSymbolAddress((void**)&t1h,   d_t1h);
    cudaGetSymbolAddress((void**)&part1, d_part1);
    cudaGetSymbolAddress((void**)&part2, d_part2);
    float* tmp1 = tmp;
    float* tmp2 = tmp + (size_t)MAXELEM;

    size_t nb = (size_t)N * CCH * sizeof(float);
    cudaMemsetAsync(tmp1, 0, 2 * nb, s);       // splits into 2 launches (>64MB)

    cudaFuncSetAttribute(conv_tc, cudaFuncAttributeMaxDynamicSharedMemorySize, SMEM_BYTES);

    const int total4 = N * (CCH / 4);
    const int total32 = N * 32;
    const float invN = 1.0f / (float)N;

    // launches: ms(0) ms(1) pack(2) shim(3) shim(4) conv1(5) <- ncu -s 5 target
    pack_x<<<592, 512, 0, s>>>(x, xh, total32);
    shim_kernel<<<1, 32, 0, s>>>(part1);
    shim_kernel<<<1, 32, 0, s>>>(part2);

    // conv1 -> BN1 partials -> fused BN+ReLU+fp16 pack
    conv_tc<<<GRID, 512, SMEM_BYTES, s>>>(xh, w1, idx_in, idx_out, tmp1, M, SMT, TT, PER);
    bn_stats<<<148, 512, 0, s>>>(tmp1, N, part1);
    bn_apply<<<592, 512, 0, s>>>(tmp1, part1, gamma1, beta1, t1h, total32, invN);

    // conv2 -> BN2 partials -> fused residual epilogue
    conv_tc<<<GRID, 512, SMEM_BYTES, s>>>(t1h, w2, idx_in, idx_out, tmp2, M, SMT, TT, PER);
    bn_stats<<<148, 512, 0, s>>>(tmp2, N, part2);
    final_kernel<<<592, 512, 0, s>>>(tmp2, x, part2, gamma2, beta2, out, total4, invN);
}